// round 14
// baseline (speedup 1.0000x reference)
#include <cuda_runtime.h>
#include <cuda_bf16.h>
#include <cstdint>

#define B4 4096
#define N2 8192
#define DZ 128
#define DF 2048
#define LCOLS 8191
#define NTILE 2080                 // 64*65/2 triangle tiles

// output layout (float32): loss[1], logits[8192*8191], labels[8192], lids_k32[8192], lids_k512[8192]
#define OUT_LOSS    0ull
#define OUT_LOGITS  1ull
#define OUT_LABELS  (1ull + (unsigned long long)N2 * LCOLS)
#define OUT_LIDS32  (OUT_LABELS + N2)
#define OUT_LIDS512 (OUT_LIDS32 + N2)

// scratch (device globals: allocation-free per harness rules)
__device__ __nv_bfloat16 g_fhi[(size_t)N2 * DF];
__device__ __nv_bfloat16 g_flo[(size_t)N2 * DF];
__device__ __nv_bfloat16 g_zhi[N2 * DZ];
__device__ __nv_bfloat16 g_zlo[N2 * DZ];
__device__ float g_fn[N2];
__device__ float g_D[(size_t)N2 * N2];     // 256 MiB
__device__ float g_ls[64 * N2];            // per-(tile-slot,row) exp partial sums
__device__ float g_lossper[N2];

// ---------------------------------------------------------------------------
// PTX helpers (plain sm_103-safe: mma.sync / ldmatrix / cp.async only)
// ---------------------------------------------------------------------------
__device__ __forceinline__ uint32_t smem_u32(const void* p) {
    uint32_t a;
    asm("{ .reg .u64 t; cvta.to.shared.u64 t, %1; cvt.u32.u64 %0, t; }" : "=r"(a) : "l"(p));
    return a;
}

#define CP_ASYNC16(dst, src) \
    asm volatile("cp.async.cg.shared.global [%0], [%1], 16;" :: "r"(dst), "l"(src) : "memory")
#define CP_COMMIT() asm volatile("cp.async.commit_group;" ::: "memory")
#define CP_WAIT1()  asm volatile("cp.async.wait_group 1;" ::: "memory")
#define CP_WAIT0()  asm volatile("cp.async.wait_group 0;" ::: "memory")

#define LDSM4(r, addr) \
    asm volatile("ldmatrix.sync.aligned.m8n8.x4.shared.b16 {%0,%1,%2,%3}, [%4];" \
        : "=r"((r)[0]), "=r"((r)[1]), "=r"((r)[2]), "=r"((r)[3]) : "r"(addr))

#define MMA16816(d, a, b0, b1) \
    asm volatile("mma.sync.aligned.m16n8k16.row.col.f32.bf16.bf16.f32 " \
        "{%0,%1,%2,%3}, {%4,%5,%6,%7}, {%8,%9}, {%0,%1,%2,%3};" \
        : "+f"((d)[0]), "+f"((d)[1]), "+f"((d)[2]), "+f"((d)[3]) \
        : "r"((a)[0]), "r"((a)[1]), "r"((a)[2]), "r"((a)[3]), "r"(b0), "r"(b1))

// off-diag column mapping (row gi, logical col gj) -> packed col, -1 = diag
__device__ __forceinline__ int colmap(int gi, int gj) {
    if (gi < B4) {
        if (gj >= B4) return gj - B4;
        if (gj == gi) return -1;
        return B4 + gj - (gj > gi ? 1 : 0);
    } else {
        if (gj < B4) return gj;
        if (gj == gi) return -1;
        return gj - (gj > gi ? 1 : 0);
    }
}

// linear tile id -> (br, bc) with 0 <= br <= bc < 64
__device__ __forceinline__ void tri_decode(int t, int& br, int& bc) {
    int row = 0, rem = t;
    #pragma unroll 1
    while (rem >= 64 - row) { rem -= 64 - row; row++; }
    br = row; bc = row + rem;
}

// ---------------------------------------------------------------------------
// prep: f squared norms + bf16 splits (vectorized), z normalize, labels
// ---------------------------------------------------------------------------
__global__ void __launch_bounds__(256) prep_kernel(
    const float* __restrict__ z0, const float* __restrict__ z1,
    const float* __restrict__ f0, const float* __restrict__ f1,
    float* __restrict__ out)
{
    int r = blockIdx.x;
    int tid = threadIdx.x;
    __shared__ float sred[256];

    const float* f = (r < B4) ? (f0 + (size_t)r * DF) : (f1 + (size_t)(r - B4) * DF);
    float s = 0.f;
    #pragma unroll
    for (int p = 0; p < 2; p++) {
        int j = tid * 8 + p * 4;               // 256*8 = 2048 exactly
        float4 v = *(const float4*)&f[j];
        s += v.x * v.x + v.y * v.y + v.z * v.z + v.w * v.w;
        __nv_bfloat162 h01 = __floats2bfloat162_rn(v.x, v.y);
        __nv_bfloat162 h23 = __floats2bfloat162_rn(v.z, v.w);
        __nv_bfloat162 l01 = __floats2bfloat162_rn(v.x - __bfloat162float(h01.x),
                                                   v.y - __bfloat162float(h01.y));
        __nv_bfloat162 l23 = __floats2bfloat162_rn(v.z - __bfloat162float(h23.x),
                                                   v.w - __bfloat162float(h23.y));
        *(__nv_bfloat162*)&g_fhi[(size_t)r * DF + j]     = h01;
        *(__nv_bfloat162*)&g_fhi[(size_t)r * DF + j + 2] = h23;
        *(__nv_bfloat162*)&g_flo[(size_t)r * DF + j]     = l01;
        *(__nv_bfloat162*)&g_flo[(size_t)r * DF + j + 2] = l23;
    }
    sred[tid] = s; __syncthreads();
    for (int st = 128; st > 0; st >>= 1) { if (tid < st) sred[tid] += sred[tid + st]; __syncthreads(); }
    if (tid == 0) g_fn[r] = sred[0];
    __syncthreads();

    const float* z = (r < B4) ? (z0 + (size_t)r * DZ) : (z1 + (size_t)(r - B4) * DZ);
    float v = (tid < DZ) ? z[tid] : 0.f;
    sred[tid] = v * v; __syncthreads();
    for (int st = 128; st > 0; st >>= 1) { if (tid < st) sred[tid] += sred[tid + st]; __syncthreads(); }
    float inv = 1.f / fmaxf(sqrtf(sred[0]), 1e-12f);
    if (tid < DZ) {
        float zn = v * inv;
        __nv_bfloat16 h = __float2bfloat16(zn);
        g_zhi[(size_t)r * DZ + tid] = h;
        g_zlo[(size_t)r * DZ + tid] = __float2bfloat16(zn - __bfloat162float(h));
    }
    if (tid == 0) out[OUT_LABELS + r] = (float)(r & (B4 - 1));
}

// ===========================================================================
// shared GEMM building blocks: CTA 128x128, warp 32x64, BK=32, 2-stage,
// 2 CTAs/SM co-residency. ROWB=80 (64B data + 16B pad).
// ===========================================================================
#define GSTG 40960                // Ah 10240 | Al 10240 | Bh 10240 | Bl 10240
#define G_AL 10240
#define G_BH 20480
#define G_BL 30720
#define ROWB 80
#define GSMEM_DYN (2 * GSTG)      // 81920 -> 2 CTAs/SM

template<int KD>
__device__ __forceinline__ void load_stage_g(
    uint32_t sb, const __nv_bfloat16* __restrict__ hi, const __nv_bfloat16* __restrict__ lo,
    int aBase, int bBase, int kt)
{
    int tid = threadIdx.x;
    #pragma unroll
    for (int p = 0; p < 2; p++) {
        int c = tid + p * 256;
        int row = c >> 2, ch = c & 3;
        size_t offA = (size_t)(aBase + row) * KD + kt + ch * 8;
        size_t offB = (size_t)(bBase + row) * KD + kt + ch * 8;
        uint32_t d = sb + row * ROWB + ch * 16;
        CP_ASYNC16(d,        hi + offA);
        CP_ASYNC16(d + G_AL, lo + offA);
        CP_ASYNC16(d + G_BH, hi + offB);
        CP_ASYNC16(d + G_BL, lo + offB);
    }
}

template<int KD>
__device__ __forceinline__ void gemm_mainloop(
    uint32_t sb, const __nv_bfloat16* hi, const __nv_bfloat16* lo,
    int aBase, int bBase, float acc[2][8][4])
{
    const int tid = threadIdx.x, wid = tid >> 5, lane = tid & 31;
    const int warpM = (wid & 3) * 32, warpN = (wid >> 2) * 64;
    const int aRow = lane & 15, aChunk = (lane >> 4) & 1;
    const int bRow = (lane & 7) | ((lane & 16) >> 1);
    const int bChunk = (lane >> 3) & 1;

    load_stage_g<KD>(sb, hi, lo, aBase, bBase, 0);
    CP_COMMIT();

    const int NK = KD / 32;
    for (int it = 0; it < NK; it++) {
        const int s = it & 1;
        if (it + 1 < NK) {
            load_stage_g<KD>(sb + (s ^ 1) * GSTG, hi, lo, aBase, bBase, (it + 1) * 32);
            CP_COMMIT();
            CP_WAIT1();
        } else {
            CP_WAIT0();
        }
        __syncthreads();

        const uint32_t Ab = sb + s * GSTG;
        const uint32_t Bb = Ab + G_BH;
        #pragma unroll
        for (int ks = 0; ks < 2; ks++) {
            uint32_t ah[2][4], al[2][4], bh[4][4], bl[4][4];
            uint32_t aAddr = Ab + (warpM + aRow) * ROWB + ks * 32 + aChunk * 16;
            LDSM4(ah[0], aAddr);
            LDSM4(ah[1], aAddr + 16 * ROWB);
            LDSM4(al[0], aAddr + G_AL);
            LDSM4(al[1], aAddr + G_AL + 16 * ROWB);
            uint32_t bAddr = Bb + (warpN + bRow) * ROWB + ks * 32 + bChunk * 16;
            #pragma unroll
            for (int nt = 0; nt < 4; nt++) {
                LDSM4(bh[nt], bAddr + nt * 16 * ROWB);
                LDSM4(bl[nt], bAddr + (G_BL - G_BH) + nt * 16 * ROWB);
            }
            #pragma unroll
            for (int mt = 0; mt < 2; mt++)
                #pragma unroll
                for (int j = 0; j < 8; j++)
                    MMA16816(acc[mt][j], ah[mt], bh[j >> 1][(j & 1) * 2], bh[j >> 1][(j & 1) * 2 + 1]);
            #pragma unroll
            for (int mt = 0; mt < 2; mt++)
                #pragma unroll
                for (int j = 0; j < 8; j++)
                    MMA16816(acc[mt][j], ah[mt], bl[j >> 1][(j & 1) * 2], bl[j >> 1][(j & 1) * 2 + 1]);
            #pragma unroll
            for (int mt = 0; mt < 2; mt++)
                #pragma unroll
                for (int j = 0; j < 8; j++)
                    MMA16816(acc[mt][j], al[mt], bh[j >> 1][(j & 1) * 2], bh[j >> 1][(j & 1) * 2 + 1]);
        }
        __syncthreads();
    }
}

// ===========================================================================
// fused GEMM kernel: blocks [0, NTILE) = dist tiles, [NTILE, 2*NTILE) = logits
// tiles. Same smem footprint both paths (80 KB dyn), 2 CTAs/SM.
// ===========================================================================
__global__ void __launch_bounds__(256, 2) fused_gemm_kernel(float* __restrict__ out)
{
    extern __shared__ char smem[];
    uint32_t sb = smem_u32(smem);
    const int tid = threadIdx.x, wid = tid >> 5, lane = tid & 31;
    const int warpM = (wid & 3) * 32, warpN = (wid >> 2) * 64;
    __shared__ float sNi[128], sNj[128];

    float acc[2][8][4];
    #pragma unroll
    for (int m = 0; m < 2; m++)
        #pragma unroll
        for (int j = 0; j < 8; j++)
            #pragma unroll
            for (int q = 0; q < 4; q++) acc[m][j][q] = 0.f;

    if (blockIdx.x < NTILE) {
        // ------------------------- dist tile -------------------------
        int br, bc;
        tri_decode(blockIdx.x, br, bc);
        const int aBase = br * 128, bBase = bc * 128;

        gemm_mainloop<DF>(sb, &g_fhi[0], &g_flo[0], aBase, bBase, acc);

        if (tid < 128) sNi[tid] = g_fn[aBase + tid];
        else           sNj[tid - 128] = g_fn[bBase + tid - 128];
        __syncthreads();

        float* st = (float*)smem;   // [128][129]
        #pragma unroll
        for (int mt = 0; mt < 2; mt++) {
            const int r0 = warpM + mt * 16 + (lane >> 2);
            #pragma unroll
            for (int j = 0; j < 8; j++) {
                const int c0 = warpN + (j >> 1) * 16 + (j & 1) * 8 + 2 * (lane & 3);
                #pragma unroll
                for (int q = 0; q < 4; q++) {
                    const int rr = r0 + (q >> 1) * 8;
                    const int cc = c0 + (q & 1);
                    st[rr * 129 + cc] = fmaxf(sNi[rr] + sNj[cc] - 2.f * acc[mt][j][q], 0.f);
                }
            }
        }
        __syncthreads();

        for (int x = tid; x < 128 * 128; x += 256) {
            int mm = x >> 7, cc = x & 127;
            g_D[(size_t)(aBase + mm) * N2 + (bBase + cc)] = st[mm * 129 + cc];
        }
        if (bc > br) {
            for (int x = tid; x < 128 * 128; x += 256) {
                int rc = x >> 7, cm = x & 127;
                g_D[(size_t)(bBase + rc) * N2 + (aBase + cm)] = st[cm * 129 + rc];
            }
        }
    } else {
        // ------------------------- logits tile -------------------------
        int br, bc;
        tri_decode(blockIdx.x - NTILE, br, bc);
        const int aBase = br * 128, bBase = bc * 128;

        gemm_mainloop<DZ>(sb, &g_zhi[0], &g_zlo[0], aBase, bBase, acc);

        float* st = (float*)smem;
        #pragma unroll
        for (int mt = 0; mt < 2; mt++) {
            const int r0 = warpM + mt * 16 + (lane >> 2);
            #pragma unroll
            for (int j = 0; j < 8; j++) {
                const int c0 = warpN + (j >> 1) * 16 + (j & 1) * 8 + 2 * (lane & 3);
                #pragma unroll
                for (int q = 0; q < 4; q++)
                    st[(r0 + (q >> 1) * 8) * 129 + c0 + (q & 1)] = 2.f * acc[mt][j][q];
            }
        }
        __syncthreads();

        for (int x = tid; x < 128 * 128; x += 256) {
            int mm = x >> 7, cc = x & 127;
            int col = colmap(aBase + mm, bBase + cc);
            if (col >= 0) out[OUT_LOGITS + (size_t)(aBase + mm) * LCOLS + col] = st[mm * 129 + cc];
        }
        if (bc > br) {
            for (int x = tid; x < 128 * 128; x += 256) {
                int rc = x >> 7, cm = x & 127;
                int col = colmap(bBase + rc, aBase + cm);
                if (col >= 0) out[OUT_LOGITS + (size_t)(bBase + rc) * LCOLS + col] = st[cm * 129 + rc];
            }
        }
        __syncthreads();

        // fused exp + row/col softmax-denominator partials
        for (int x = tid; x < 128 * 128; x += 256) {
            int mm = x >> 7, cc = x & 127;
            float e = __expf(st[mm * 129 + cc]);
            if (br == bc && mm == cc) e = 0.f;     // exclude diagonal
            st[mm * 129 + cc] = e;
        }
        __syncthreads();

        {   // row sums -> slot bc, rows aBase..aBase+127 (2 threads per row)
            int row = tid >> 1, half = tid & 1;
            float s = 0.f;
            #pragma unroll 4
            for (int c2 = half * 64; c2 < half * 64 + 64; c2++) s += st[row * 129 + c2];
            s += __shfl_xor_sync(0xFFFFFFFFu, s, 1);
            if (half == 0) g_ls[(size_t)bc * N2 + aBase + row] = s;
        }
        if (bc > br) {   // col sums -> slot br, rows bBase..bBase+127
            int col = tid >> 1, half = tid & 1;
            float s = 0.f;
            #pragma unroll 4
            for (int r2 = half * 64; r2 < half * 64 + 64; r2++) s += st[r2 * 129 + col];
            s += __shfl_xor_sync(0xFFFFFFFFu, s, 1);
            if (half == 0) g_ls[(size_t)br * N2 + bBase + col] = s;
        }
    }
}

// ---------------------------------------------------------------------------
// loss_final: per row, S = sum of 64 partials; pos = 2*dot(z0n, z1n)
// ---------------------------------------------------------------------------
__global__ void __launch_bounds__(128) loss_final_kernel()
{
    int r = blockIdx.x, tid = threadIdx.x;
    int pr = (r < B4) ? r + B4 : r - B4;

    float a = (float)g_zhi[(size_t)r * DZ + tid] + (float)g_zlo[(size_t)r * DZ + tid];
    float b = (float)g_zhi[(size_t)pr * DZ + tid] + (float)g_zlo[(size_t)pr * DZ + tid];
    float p = a * b;
    float S = (tid < 64) ? g_ls[(size_t)tid * N2 + r] : 0.f;

    #pragma unroll
    for (int d = 16; d > 0; d >>= 1) {
        p += __shfl_xor_sync(0xFFFFFFFFu, p, d);
        S += __shfl_xor_sync(0xFFFFFFFFu, S, d);
    }
    __shared__ float sp[4], sS[4];
    if ((tid & 31) == 0) { sp[tid >> 5] = p; sS[tid >> 5] = S; }
    __syncthreads();
    if (tid == 0) {
        float P = sp[0] + sp[1] + sp[2] + sp[3];
        float SS = sS[0] + sS[1] + sS[2] + sS[3];
        g_lossper[r] = logf(SS) - 2.f * P;
    }
}

__global__ void __launch_bounds__(256) finalize_kernel(float* __restrict__ out)
{
    __shared__ double sred[256];
    int tid = threadIdx.x;
    double s = 0.0;
    for (int j = tid; j < N2; j += 256) s += (double)g_lossper[j];
    sred[tid] = s; __syncthreads();
    for (int st = 128; st > 0; st >>= 1) { if (tid < st) sred[tid] += sred[tid + st]; __syncthreads(); }
    if (tid == 0) out[OUT_LOSS] = (float)(sred[0] / (double)N2);
}

// ---------------------------------------------------------------------------
// select: linear-bin select of rank-32 AND rank-512 + per-bin log prefix sums
// (3 key scans total; no final LID scan).
//   scan 1: load keys + min/max
//   scan 2: 4096 linear bins: count hist + logsum (0.5 ln d2 - lnRef)
//   scan 3: collect boundary-bin candidates; exact K by rank count;
//           S_k = prefixLog + inBinLog - cnt*(lnK - lnRef)
// ---------------------------------------------------------------------------
#define CANDCAP 1024

__device__ __forceinline__ void scan_find(
    const unsigned* __restrict__ hist, int kk,
    unsigned* s_bin, int* s_kk, unsigned* wtot)
{
    int tid = threadIdx.x;
    unsigned c[8], tsum = 0;
    #pragma unroll
    for (int b = 0; b < 8; b++) { c[b] = hist[tid * 8 + b]; tsum += c[b]; }
    unsigned v = tsum;
    #pragma unroll
    for (int d = 1; d < 32; d <<= 1) {
        unsigned n = __shfl_up_sync(0xFFFFFFFFu, v, d);
        if ((tid & 31) >= d) v += n;
    }
    if ((tid & 31) == 31) wtot[tid >> 5] = v;
    __syncthreads();
    if (tid < 16) {
        unsigned t = wtot[tid];
        #pragma unroll
        for (int d = 1; d < 16; d <<= 1) {
            unsigned n = __shfl_up_sync(0xFFFFu, t, d);
            if (tid >= d) t += n;
        }
        wtot[tid] = t;
    }
    __syncthreads();
    unsigned incl = v + ((tid >= 32) ? wtot[(tid >> 5) - 1] : 0u);
    unsigned excl = incl - tsum;
    if ((unsigned)kk > excl && (unsigned)kk <= incl) {
        unsigned cum = excl;
        #pragma unroll
        for (int b = 0; b < 8; b++) {
            if ((unsigned)kk <= cum + c[b]) { *s_bin = tid * 8 + b; *s_kk = kk - (int)cum; break; }
            cum += c[b];
        }
    }
    __syncthreads();
}

__global__ void __launch_bounds__(512) select_kernel(float* __restrict__ out)
{
    int r = blockIdx.x, tid = threadIdx.x;
    int lane = tid & 31;
    __shared__ unsigned skey[N2];           // 32 KB
    __shared__ unsigned hist[4096];         // 16 KB
    __shared__ float   lsum[4096];          // 16 KB
    __shared__ unsigned cand[2][CANDCAP];   // 8 KB
    __shared__ unsigned candn[2];
    __shared__ unsigned wtot[16];
    __shared__ unsigned s_bin[2];
    __shared__ int s_kkv[2];
    __shared__ unsigned s_lohi[2];
    __shared__ unsigned sK[2];
    __shared__ float s_pref[2];             // prefix log sums (bins < b)
    __shared__ float s_inlog[2];
    __shared__ int   s_incnt[2];

    // ---- scan 1: load keys + block min/max ----
    #pragma unroll
    for (int b = 0; b < 8; b++) { hist[tid + b * 512] = 0u; lsum[tid + b * 512] = 0.f; }
    if (tid < 2) { candn[tid] = 0u; s_pref[tid] = 0.f; s_inlog[tid] = 0.f; s_incnt[tid] = 0; }
    const float* drow = &g_D[(size_t)r * N2];
    unsigned lmin = 0xFFFFFFFFu, lmax = 0u;
    for (int j = tid; j < N2; j += 512) {
        unsigned kv = (j == r) ? 0xFFFFFFFFu : __float_as_uint(drow[j]);
        skey[j] = kv;
        lmin = min(lmin, kv);
        lmax = max(lmax, (j == r) ? 0u : kv);
    }
    #pragma unroll
    for (int d = 16; d > 0; d >>= 1) {
        lmin = min(lmin, __shfl_xor_sync(0xFFFFFFFFu, lmin, d));
        lmax = max(lmax, __shfl_xor_sync(0xFFFFFFFFu, lmax, d));
    }
    if (lane == 0) wtot[tid >> 5] = lmin;
    __syncthreads();
    if (tid == 0) {
        unsigned m = 0xFFFFFFFFu;
        #pragma unroll
        for (int w = 0; w < 16; w++) m = min(m, wtot[w]);
        s_lohi[0] = m;
    }
    __syncthreads();
    if (lane == 0) wtot[tid >> 5] = lmax;
    __syncthreads();
    if (tid == 0) {
        unsigned m = 0u;
        #pragma unroll
        for (int w = 0; w < 16; w++) m = max(m, wtot[w]);
        s_lohi[1] = m;
    }
    __syncthreads();

    const unsigned lo = s_lohi[0];
    const float scale = 4096.0f / ((float)(s_lohi[1] - lo) + 1.0f);
    const float lnRef = 0.5f * logf(fmaxf(__uint_as_float(lo), 1e-30f));

    // ---- scan 2: linear hist + per-bin log sums ----
    for (int j = tid; j < N2; j += 512) {
        unsigned kv = skey[j];
        unsigned bin = min(4095u, (unsigned)((float)(kv - lo) * scale));
        atomicAdd(&hist[bin], 1u);
        if (kv != 0xFFFFFFFFu)
            atomicAdd(&lsum[bin], 0.5f * logf(__uint_as_float(kv)) - lnRef);
    }
    __syncthreads();
    scan_find(hist, 32,  &s_bin[0], &s_kkv[0], wtot);
    scan_find(hist, 512, &s_bin[1], &s_kkv[1], wtot);
    const unsigned b32 = s_bin[0], b512 = s_bin[1];
    const int kk32 = s_kkv[0], kk512 = s_kkv[1];
    __syncthreads();

    // prefix log sums over bins < b32 / < b512 (warp-reduced + atomic)
    {
        float a32 = 0.f, a512 = 0.f;
        #pragma unroll
        for (int b = 0; b < 8; b++) {
            unsigned bin = tid * 8 + b;
            float v = lsum[bin];
            if (bin < b32)  a32 += v;
            if (bin < b512) a512 += v;
        }
        #pragma unroll
        for (int d = 16; d > 0; d >>= 1) {
            a32 += __shfl_xor_sync(0xFFFFFFFFu, a32, d);
            a512 += __shfl_xor_sync(0xFFFFFFFFu, a512, d);
        }
        if (lane == 0) { atomicAdd(&s_pref[0], a32); atomicAdd(&s_pref[1], a512); }
    }

    // ---- scan 3: collect boundary-bin candidates ----
    for (int j = tid; j < N2; j += 512) {
        unsigned kv = skey[j];
        unsigned bin = min(4095u, (unsigned)((float)(kv - lo) * scale));
        if (bin == b32) {
            unsigned idx = atomicAdd(&candn[0], 1u);
            if (idx < CANDCAP) cand[0][idx] = kv;
        }
        if (bin == b512 && b512 != b32) {
            unsigned idx = atomicAdd(&candn[1], 1u);
            if (idx < CANDCAP) cand[1][idx] = kv;
        }
    }
    __syncthreads();

    // exact K via rank count among candidates (duplicate-safe)
    {
        int c0 = (int)min(candn[0], (unsigned)CANDCAP);
        for (int i = tid; i < c0; i += 512) {
            unsigned v = cand[0][i];
            int sm = 0, eq = 0;
            for (int j = 0; j < c0; j++) {
                unsigned w = cand[0][j];
                sm += (w < v); eq += (w == v);
            }
            if (sm < kk32 && kk32 <= sm + eq) sK[0] = v;
        }
        const unsigned* c512arr = (b512 == b32) ? cand[0] : cand[1];
        int c1 = (b512 == b32) ? c0 : (int)min(candn[1], (unsigned)CANDCAP);
        for (int i = tid; i < c1; i += 512) {
            unsigned v = c512arr[i];
            int sm = 0, eq = 0;
            for (int j = 0; j < c1; j++) {
                unsigned w = c512arr[j];
                sm += (w < v); eq += (w == v);
            }
            if (sm < kk512 && kk512 <= sm + eq) sK[1] = v;
        }
    }
    __syncthreads();
    const unsigned K32 = sK[0];
    const unsigned K512 = sK[1];

    // boundary-bin contributions: count + log sums of kv < K (tiny arrays)
    {
        int c0 = (int)min(candn[0], (unsigned)CANDCAP);
        for (int i = tid; i < c0; i += 512) {
            unsigned v = cand[0][i];
            if (v < K32) {
                atomicAdd(&s_inlog[0], 0.5f * logf(__uint_as_float(v)) - lnRef);
                atomicAdd(&s_incnt[0], 1);
            }
        }
        const unsigned* c512arr = (b512 == b32) ? cand[0] : cand[1];
        int c1 = (b512 == b32) ? c0 : (int)min(candn[1], (unsigned)CANDCAP);
        for (int i = tid; i < c1; i += 512) {
            unsigned v = c512arr[i];
            if (v < K512) {
                atomicAdd(&s_inlog[1], 0.5f * logf(__uint_as_float(v)) - lnRef);
                atomicAdd(&s_incnt[1], 1);
            }
        }
    }
    __syncthreads();

    if (tid == 0) {
        int cnt32 = (32 - kk32) + s_incnt[0];            // excl + in-bin below K
        float S32 = s_pref[0] + s_inlog[0]
                  - (float)cnt32 * (0.5f * logf(__uint_as_float(K32)) - lnRef);
        out[OUT_LIDS32 + r] = -32.f / S32;
    } else if (tid == 32) {
        int cnt512 = (512 - kk512) + s_incnt[1];
        float S512 = s_pref[1] + s_inlog[1]
                   - (float)cnt512 * (0.5f * logf(__uint_as_float(K512)) - lnRef);
        out[OUT_LIDS512 + r] = -512.f / S512;
    }
}

// ---------------------------------------------------------------------------
extern "C" void kernel_launch(void* const* d_in, const int* in_sizes, int n_in,
                              void* d_out, int out_size)
{
    const float* z0 = (const float*)d_in[0];
    const float* z1 = (const float*)d_in[1];
    const float* f0 = (const float*)d_in[2];
    const float* f1 = (const float*)d_in[3];
    float* out = (float*)d_out;

    cudaFuncSetAttribute(fused_gemm_kernel,
                         cudaFuncAttributeMaxDynamicSharedMemorySize, GSMEM_DYN);

    // order chosen so ncu's capture slot lands on select_kernel (4th launch)
    prep_kernel<<<N2, 256>>>(z0, z1, f0, f1, out);
    fused_gemm_kernel<<<2 * NTILE, 256, GSMEM_DYN>>>(out);
    loss_final_kernel<<<N2, 128>>>();
    select_kernel<<<N2, 512>>>(out);
    finalize_kernel<<<1, 256>>>(out);
}

// round 15
// speedup vs baseline: 1.1321x; 1.1321x over previous
#include <cuda_runtime.h>
#include <cuda_bf16.h>
#include <cstdint>

#define B4 4096
#define N2 8192
#define DZ 128
#define DF 2048
#define LCOLS 8191
#define NTILE 2080                 // 64*65/2 triangle tiles

// output layout (float32): loss[1], logits[8192*8191], labels[8192], lids_k32[8192], lids_k512[8192]
#define OUT_LOSS    0ull
#define OUT_LOGITS  1ull
#define OUT_LABELS  (1ull + (unsigned long long)N2 * LCOLS)
#define OUT_LIDS32  (OUT_LABELS + N2)
#define OUT_LIDS512 (OUT_LIDS32 + N2)

// scratch (device globals: allocation-free per harness rules)
__device__ __nv_bfloat16 g_fhi[(size_t)N2 * DF];
__device__ __nv_bfloat16 g_flo[(size_t)N2 * DF];
__device__ __nv_bfloat16 g_zhi[N2 * DZ];
__device__ __nv_bfloat16 g_zlo[N2 * DZ];
__device__ float g_fn[N2];
__device__ float g_D[(size_t)N2 * N2];     // 256 MiB
__device__ float g_ls[64 * N2];            // per-(tile-slot,row) exp partial sums
__device__ float g_lossper[N2];

// ---------------------------------------------------------------------------
// PTX helpers (plain sm_103-safe: mma.sync / ldmatrix / cp.async only)
// ---------------------------------------------------------------------------
__device__ __forceinline__ uint32_t smem_u32(const void* p) {
    uint32_t a;
    asm("{ .reg .u64 t; cvta.to.shared.u64 t, %1; cvt.u32.u64 %0, t; }" : "=r"(a) : "l"(p));
    return a;
}

#define CP_ASYNC16(dst, src) \
    asm volatile("cp.async.cg.shared.global [%0], [%1], 16;" :: "r"(dst), "l"(src) : "memory")
#define CP_COMMIT() asm volatile("cp.async.commit_group;" ::: "memory")
#define CP_WAIT1()  asm volatile("cp.async.wait_group 1;" ::: "memory")
#define CP_WAIT0()  asm volatile("cp.async.wait_group 0;" ::: "memory")

#define LDSM4(r, addr) \
    asm volatile("ldmatrix.sync.aligned.m8n8.x4.shared.b16 {%0,%1,%2,%3}, [%4];" \
        : "=r"((r)[0]), "=r"((r)[1]), "=r"((r)[2]), "=r"((r)[3]) : "r"(addr))

#define MMA16816(d, a, b0, b1) \
    asm volatile("mma.sync.aligned.m16n8k16.row.col.f32.bf16.bf16.f32 " \
        "{%0,%1,%2,%3}, {%4,%5,%6,%7}, {%8,%9}, {%0,%1,%2,%3};" \
        : "+f"((d)[0]), "+f"((d)[1]), "+f"((d)[2]), "+f"((d)[3]) \
        : "r"((a)[0]), "r"((a)[1]), "r"((a)[2]), "r"((a)[3]), "r"(b0), "r"(b1))

// off-diag column mapping (row gi, logical col gj) -> packed col, -1 = diag
__device__ __forceinline__ int colmap(int gi, int gj) {
    if (gi < B4) {
        if (gj >= B4) return gj - B4;
        if (gj == gi) return -1;
        return B4 + gj - (gj > gi ? 1 : 0);
    } else {
        if (gj < B4) return gj;
        if (gj == gi) return -1;
        return gj - (gj > gi ? 1 : 0);
    }
}

// linear tile id -> (br, bc) with 0 <= br <= bc < 64
__device__ __forceinline__ void tri_decode(int t, int& br, int& bc) {
    int row = 0, rem = t;
    #pragma unroll 1
    while (rem >= 64 - row) { rem -= 64 - row; row++; }
    br = row; bc = row + rem;
}

// ---------------------------------------------------------------------------
// prep: f squared norms + bf16 splits (vectorized), z normalize, labels
// ---------------------------------------------------------------------------
__global__ void __launch_bounds__(256) prep_kernel(
    const float* __restrict__ z0, const float* __restrict__ z1,
    const float* __restrict__ f0, const float* __restrict__ f1,
    float* __restrict__ out)
{
    int r = blockIdx.x;
    int tid = threadIdx.x;
    __shared__ float sred[256];

    const float* f = (r < B4) ? (f0 + (size_t)r * DF) : (f1 + (size_t)(r - B4) * DF);
    float s = 0.f;
    #pragma unroll
    for (int p = 0; p < 2; p++) {
        int j = tid * 8 + p * 4;               // 256*8 = 2048 exactly
        float4 v = *(const float4*)&f[j];
        s += v.x * v.x + v.y * v.y + v.z * v.z + v.w * v.w;
        __nv_bfloat162 h01 = __floats2bfloat162_rn(v.x, v.y);
        __nv_bfloat162 h23 = __floats2bfloat162_rn(v.z, v.w);
        __nv_bfloat162 l01 = __floats2bfloat162_rn(v.x - __bfloat162float(h01.x),
                                                   v.y - __bfloat162float(h01.y));
        __nv_bfloat162 l23 = __floats2bfloat162_rn(v.z - __bfloat162float(h23.x),
                                                   v.w - __bfloat162float(h23.y));
        *(__nv_bfloat162*)&g_fhi[(size_t)r * DF + j]     = h01;
        *(__nv_bfloat162*)&g_fhi[(size_t)r * DF + j + 2] = h23;
        *(__nv_bfloat162*)&g_flo[(size_t)r * DF + j]     = l01;
        *(__nv_bfloat162*)&g_flo[(size_t)r * DF + j + 2] = l23;
    }
    sred[tid] = s; __syncthreads();
    for (int st = 128; st > 0; st >>= 1) { if (tid < st) sred[tid] += sred[tid + st]; __syncthreads(); }
    if (tid == 0) g_fn[r] = sred[0];
    __syncthreads();

    const float* z = (r < B4) ? (z0 + (size_t)r * DZ) : (z1 + (size_t)(r - B4) * DZ);
    float v = (tid < DZ) ? z[tid] : 0.f;
    sred[tid] = v * v; __syncthreads();
    for (int st = 128; st > 0; st >>= 1) { if (tid < st) sred[tid] += sred[tid + st]; __syncthreads(); }
    float inv = 1.f / fmaxf(sqrtf(sred[0]), 1e-12f);
    if (tid < DZ) {
        float zn = v * inv;
        __nv_bfloat16 h = __float2bfloat16(zn);
        g_zhi[(size_t)r * DZ + tid] = h;
        g_zlo[(size_t)r * DZ + tid] = __float2bfloat16(zn - __bfloat162float(h));
    }
    if (tid == 0) out[OUT_LABELS + r] = (float)(r & (B4 - 1));
}

// ===========================================================================
// shared GEMM building blocks: CTA 128x128, warp 32x64, BK=32, 2-stage,
// 2 CTAs/SM co-residency. ROWB=80 (64B data + 16B pad).
// ===========================================================================
#define GSTG 40960                // Ah 10240 | Al 10240 | Bh 10240 | Bl 10240
#define G_AL 10240
#define G_BH 20480
#define G_BL 30720
#define ROWB 80
#define GSMEM_DYN (2 * GSTG)      // 81920 -> 2 CTAs/SM

template<int KD>
__device__ __forceinline__ void load_stage_g(
    uint32_t sb, const __nv_bfloat16* __restrict__ hi, const __nv_bfloat16* __restrict__ lo,
    int aBase, int bBase, int kt)
{
    int tid = threadIdx.x;
    #pragma unroll
    for (int p = 0; p < 2; p++) {
        int c = tid + p * 256;
        int row = c >> 2, ch = c & 3;
        size_t offA = (size_t)(aBase + row) * KD + kt + ch * 8;
        size_t offB = (size_t)(bBase + row) * KD + kt + ch * 8;
        uint32_t d = sb + row * ROWB + ch * 16;
        CP_ASYNC16(d,        hi + offA);
        CP_ASYNC16(d + G_AL, lo + offA);
        CP_ASYNC16(d + G_BH, hi + offB);
        CP_ASYNC16(d + G_BL, lo + offB);
    }
}

template<int KD>
__device__ __forceinline__ void gemm_mainloop(
    uint32_t sb, const __nv_bfloat16* hi, const __nv_bfloat16* lo,
    int aBase, int bBase, float acc[2][8][4])
{
    const int tid = threadIdx.x, wid = tid >> 5, lane = tid & 31;
    const int warpM = (wid & 3) * 32, warpN = (wid >> 2) * 64;
    const int aRow = lane & 15, aChunk = (lane >> 4) & 1;
    const int bRow = (lane & 7) | ((lane & 16) >> 1);
    const int bChunk = (lane >> 3) & 1;

    load_stage_g<KD>(sb, hi, lo, aBase, bBase, 0);
    CP_COMMIT();

    const int NK = KD / 32;
    for (int it = 0; it < NK; it++) {
        const int s = it & 1;
        if (it + 1 < NK) {
            load_stage_g<KD>(sb + (s ^ 1) * GSTG, hi, lo, aBase, bBase, (it + 1) * 32);
            CP_COMMIT();
            CP_WAIT1();
        } else {
            CP_WAIT0();
        }
        __syncthreads();

        const uint32_t Ab = sb + s * GSTG;
        const uint32_t Bb = Ab + G_BH;
        #pragma unroll
        for (int ks = 0; ks < 2; ks++) {
            uint32_t ah[2][4], al[2][4], bh[4][4], bl[4][4];
            uint32_t aAddr = Ab + (warpM + aRow) * ROWB + ks * 32 + aChunk * 16;
            LDSM4(ah[0], aAddr);
            LDSM4(ah[1], aAddr + 16 * ROWB);
            LDSM4(al[0], aAddr + G_AL);
            LDSM4(al[1], aAddr + G_AL + 16 * ROWB);
            uint32_t bAddr = Bb + (warpN + bRow) * ROWB + ks * 32 + bChunk * 16;
            #pragma unroll
            for (int nt = 0; nt < 4; nt++) {
                LDSM4(bh[nt], bAddr + nt * 16 * ROWB);
                LDSM4(bl[nt], bAddr + (G_BL - G_BH) + nt * 16 * ROWB);
            }
            #pragma unroll
            for (int mt = 0; mt < 2; mt++)
                #pragma unroll
                for (int j = 0; j < 8; j++)
                    MMA16816(acc[mt][j], ah[mt], bh[j >> 1][(j & 1) * 2], bh[j >> 1][(j & 1) * 2 + 1]);
            #pragma unroll
            for (int mt = 0; mt < 2; mt++)
                #pragma unroll
                for (int j = 0; j < 8; j++)
                    MMA16816(acc[mt][j], ah[mt], bl[j >> 1][(j & 1) * 2], bl[j >> 1][(j & 1) * 2 + 1]);
            #pragma unroll
            for (int mt = 0; mt < 2; mt++)
                #pragma unroll
                for (int j = 0; j < 8; j++)
                    MMA16816(acc[mt][j], al[mt], bh[j >> 1][(j & 1) * 2], bh[j >> 1][(j & 1) * 2 + 1]);
        }
        __syncthreads();
    }
}

// ===========================================================================
// fused GEMM kernel: blocks [0, NTILE) = dist tiles, [NTILE, 2*NTILE) = logits
// tiles. Same smem footprint both paths (80 KB dyn), 2 CTAs/SM.
// ===========================================================================
__global__ void __launch_bounds__(256, 2) fused_gemm_kernel(float* __restrict__ out)
{
    extern __shared__ char smem[];
    uint32_t sb = smem_u32(smem);
    const int tid = threadIdx.x, wid = tid >> 5, lane = tid & 31;
    const int warpM = (wid & 3) * 32, warpN = (wid >> 2) * 64;
    __shared__ float sNi[128], sNj[128];

    float acc[2][8][4];
    #pragma unroll
    for (int m = 0; m < 2; m++)
        #pragma unroll
        for (int j = 0; j < 8; j++)
            #pragma unroll
            for (int q = 0; q < 4; q++) acc[m][j][q] = 0.f;

    if (blockIdx.x < NTILE) {
        // ------------------------- dist tile -------------------------
        int br, bc;
        tri_decode(blockIdx.x, br, bc);
        const int aBase = br * 128, bBase = bc * 128;

        gemm_mainloop<DF>(sb, &g_fhi[0], &g_flo[0], aBase, bBase, acc);

        if (tid < 128) sNi[tid] = g_fn[aBase + tid];
        else           sNj[tid - 128] = g_fn[bBase + tid - 128];
        __syncthreads();

        float* st = (float*)smem;   // [128][129]
        #pragma unroll
        for (int mt = 0; mt < 2; mt++) {
            const int r0 = warpM + mt * 16 + (lane >> 2);
            #pragma unroll
            for (int j = 0; j < 8; j++) {
                const int c0 = warpN + (j >> 1) * 16 + (j & 1) * 8 + 2 * (lane & 3);
                #pragma unroll
                for (int q = 0; q < 4; q++) {
                    const int rr = r0 + (q >> 1) * 8;
                    const int cc = c0 + (q & 1);
                    st[rr * 129 + cc] = fmaxf(sNi[rr] + sNj[cc] - 2.f * acc[mt][j][q], 0.f);
                }
            }
        }
        __syncthreads();

        for (int x = tid; x < 128 * 128; x += 256) {
            int mm = x >> 7, cc = x & 127;
            g_D[(size_t)(aBase + mm) * N2 + (bBase + cc)] = st[mm * 129 + cc];
        }
        if (bc > br) {
            for (int x = tid; x < 128 * 128; x += 256) {
                int rc = x >> 7, cm = x & 127;
                g_D[(size_t)(bBase + rc) * N2 + (aBase + cm)] = st[cm * 129 + rc];
            }
        }
    } else {
        // ------------------------- logits tile -------------------------
        int br, bc;
        tri_decode(blockIdx.x - NTILE, br, bc);
        const int aBase = br * 128, bBase = bc * 128;

        gemm_mainloop<DZ>(sb, &g_zhi[0], &g_zlo[0], aBase, bBase, acc);

        float* st = (float*)smem;
        #pragma unroll
        for (int mt = 0; mt < 2; mt++) {
            const int r0 = warpM + mt * 16 + (lane >> 2);
            #pragma unroll
            for (int j = 0; j < 8; j++) {
                const int c0 = warpN + (j >> 1) * 16 + (j & 1) * 8 + 2 * (lane & 3);
                #pragma unroll
                for (int q = 0; q < 4; q++)
                    st[(r0 + (q >> 1) * 8) * 129 + c0 + (q & 1)] = 2.f * acc[mt][j][q];
            }
        }
        __syncthreads();

        for (int x = tid; x < 128 * 128; x += 256) {
            int mm = x >> 7, cc = x & 127;
            int col = colmap(aBase + mm, bBase + cc);
            if (col >= 0) out[OUT_LOGITS + (size_t)(aBase + mm) * LCOLS + col] = st[mm * 129 + cc];
        }
        if (bc > br) {
            for (int x = tid; x < 128 * 128; x += 256) {
                int rc = x >> 7, cm = x & 127;
                int col = colmap(bBase + rc, aBase + cm);
                if (col >= 0) out[OUT_LOGITS + (size_t)(bBase + rc) * LCOLS + col] = st[cm * 129 + rc];
            }
        }
        __syncthreads();

        // fused exp + row/col softmax-denominator partials
        for (int x = tid; x < 128 * 128; x += 256) {
            int mm = x >> 7, cc = x & 127;
            float e = __expf(st[mm * 129 + cc]);
            if (br == bc && mm == cc) e = 0.f;     // exclude diagonal
            st[mm * 129 + cc] = e;
        }
        __syncthreads();

        {   // row sums -> slot bc, rows aBase..aBase+127 (2 threads per row)
            int row = tid >> 1, half = tid & 1;
            float s = 0.f;
            #pragma unroll 4
            for (int c2 = half * 64; c2 < half * 64 + 64; c2++) s += st[row * 129 + c2];
            s += __shfl_xor_sync(0xFFFFFFFFu, s, 1);
            if (half == 0) g_ls[(size_t)bc * N2 + aBase + row] = s;
        }
        if (bc > br) {   // col sums -> slot br, rows bBase..bBase+127
            int col = tid >> 1, half = tid & 1;
            float s = 0.f;
            #pragma unroll 4
            for (int r2 = half * 64; r2 < half * 64 + 64; r2++) s += st[r2 * 129 + col];
            s += __shfl_xor_sync(0xFFFFFFFFu, s, 1);
            if (half == 0) g_ls[(size_t)br * N2 + bBase + col] = s;
        }
    }
}

// ---------------------------------------------------------------------------
// loss_final: per row, S = sum of 64 partials; pos = 2*dot(z0n, z1n)
// ---------------------------------------------------------------------------
__global__ void __launch_bounds__(128) loss_final_kernel()
{
    int r = blockIdx.x, tid = threadIdx.x;
    int pr = (r < B4) ? r + B4 : r - B4;

    float a = (float)g_zhi[(size_t)r * DZ + tid] + (float)g_zlo[(size_t)r * DZ + tid];
    float b = (float)g_zhi[(size_t)pr * DZ + tid] + (float)g_zlo[(size_t)pr * DZ + tid];
    float p = a * b;
    float S = (tid < 64) ? g_ls[(size_t)tid * N2 + r] : 0.f;

    #pragma unroll
    for (int d = 16; d > 0; d >>= 1) {
        p += __shfl_xor_sync(0xFFFFFFFFu, p, d);
        S += __shfl_xor_sync(0xFFFFFFFFu, S, d);
    }
    __shared__ float sp[4], sS[4];
    if ((tid & 31) == 0) { sp[tid >> 5] = p; sS[tid >> 5] = S; }
    __syncthreads();
    if (tid == 0) {
        float P = sp[0] + sp[1] + sp[2] + sp[3];
        float SS = sS[0] + sS[1] + sS[2] + sS[3];
        g_lossper[r] = logf(SS) - 2.f * P;
    }
}

__global__ void __launch_bounds__(256) finalize_kernel(float* __restrict__ out)
{
    __shared__ double sred[256];
    int tid = threadIdx.x;
    double s = 0.0;
    for (int j = tid; j < N2; j += 256) s += (double)g_lossper[j];
    sred[tid] = s; __syncthreads();
    for (int st = 128; st > 0; st >>= 1) { if (tid < st) sred[tid] += sred[tid + st]; __syncthreads(); }
    if (tid == 0) out[OUT_LOSS] = (float)(sred[0] / (double)N2);
}

// ---------------------------------------------------------------------------
// select: linear-bin select of rank-32 AND rank-512, 3 key scans (uint4
// vectorized), register-accumulated prefix log sums in scan 3 (no float
// atomics in hot path, no 4th scan).
// ---------------------------------------------------------------------------
#define CANDCAP 1024

__device__ __forceinline__ void scan_find(
    const unsigned* __restrict__ hist, int kk,
    unsigned* s_bin, int* s_kk, unsigned* wtot)
{
    int tid = threadIdx.x;
    unsigned c[8], tsum = 0;
    #pragma unroll
    for (int b = 0; b < 8; b++) { c[b] = hist[tid * 8 + b]; tsum += c[b]; }
    unsigned v = tsum;
    #pragma unroll
    for (int d = 1; d < 32; d <<= 1) {
        unsigned n = __shfl_up_sync(0xFFFFFFFFu, v, d);
        if ((tid & 31) >= d) v += n;
    }
    if ((tid & 31) == 31) wtot[tid >> 5] = v;
    __syncthreads();
    if (tid < 16) {
        unsigned t = wtot[tid];
        #pragma unroll
        for (int d = 1; d < 16; d <<= 1) {
            unsigned n = __shfl_up_sync(0xFFFFu, t, d);
            if (tid >= d) t += n;
        }
        wtot[tid] = t;
    }
    __syncthreads();
    unsigned incl = v + ((tid >= 32) ? wtot[(tid >> 5) - 1] : 0u);
    unsigned excl = incl - tsum;
    if ((unsigned)kk > excl && (unsigned)kk <= incl) {
        unsigned cum = excl;
        #pragma unroll
        for (int b = 0; b < 8; b++) {
            if ((unsigned)kk <= cum + c[b]) { *s_bin = tid * 8 + b; *s_kk = kk - (int)cum; break; }
            cum += c[b];
        }
    }
    __syncthreads();
}

__global__ void __launch_bounds__(512) select_kernel(float* __restrict__ out)
{
    int r = blockIdx.x, tid = threadIdx.x;
    int lane = tid & 31;
    __shared__ unsigned skey[N2];           // 32 KB
    __shared__ unsigned hist[4096];         // 16 KB
    __shared__ unsigned cand[2][CANDCAP];   // 8 KB
    __shared__ unsigned candn[2];
    __shared__ unsigned wtot[16];
    __shared__ unsigned s_bin[2];
    __shared__ int s_kkv[2];
    __shared__ unsigned s_lohi[2];
    __shared__ unsigned sK[2];
    __shared__ float s_pref[2];
    __shared__ float s_inlog[2];
    __shared__ int   s_incnt[2];

    // ---- scan 1: vectorized load + patch diagonal + block min/max ----
    #pragma unroll
    for (int b = 0; b < 8; b++) hist[tid + b * 512] = 0u;
    if (tid < 2) { candn[tid] = 0u; s_pref[tid] = 0.f; s_inlog[tid] = 0.f; s_incnt[tid] = 0; }
    const uint4* drow4 = (const uint4*)&g_D[(size_t)r * N2];
    unsigned lmin = 0xFFFFFFFFu, lmax = 0u;
    #pragma unroll
    for (int p = 0; p < 4; p++) {
        int j4 = tid + p * 512;                  // uint4 index (2048 total)
        uint4 v = drow4[j4];
        int j = j4 * 4;
        unsigned a[4] = {v.x, v.y, v.z, v.w};
        #pragma unroll
        for (int q = 0; q < 4; q++) {
            bool dg = (j + q) == r;
            unsigned kv = dg ? 0xFFFFFFFFu : a[q];
            lmin = min(lmin, kv);
            lmax = max(lmax, dg ? 0u : kv);
            a[q] = kv;
        }
        *(uint4*)&skey[j] = make_uint4(a[0], a[1], a[2], a[3]);
    }
    #pragma unroll
    for (int d = 16; d > 0; d >>= 1) {
        lmin = min(lmin, __shfl_xor_sync(0xFFFFFFFFu, lmin, d));
        lmax = max(lmax, __shfl_xor_sync(0xFFFFFFFFu, lmax, d));
    }
    if (lane == 0) wtot[tid >> 5] = lmin;
    __syncthreads();
    if (tid == 0) {
        unsigned m = 0xFFFFFFFFu;
        #pragma unroll
        for (int w = 0; w < 16; w++) m = min(m, wtot[w]);
        s_lohi[0] = m;
    }
    __syncthreads();
    if (lane == 0) wtot[tid >> 5] = lmax;
    __syncthreads();
    if (tid == 0) {
        unsigned m = 0u;
        #pragma unroll
        for (int w = 0; w < 16; w++) m = max(m, wtot[w]);
        s_lohi[1] = m;
    }
    __syncthreads();

    const unsigned lo = s_lohi[0];
    const float scale = 4096.0f / ((float)(s_lohi[1] - lo) + 1.0f);
    const float lnRef = 0.5f * logf(fmaxf(__uint_as_float(lo), 1e-30f));

    // ---- scan 2: count histogram (spread smem atomics) ----
    const uint4* sk4 = (const uint4*)skey;
    #pragma unroll
    for (int p = 0; p < 4; p++) {
        uint4 v = sk4[tid + p * 512];
        atomicAdd(&hist[min(4095u, (unsigned)((float)(v.x - lo) * scale))], 1u);
        atomicAdd(&hist[min(4095u, (unsigned)((float)(v.y - lo) * scale))], 1u);
        atomicAdd(&hist[min(4095u, (unsigned)((float)(v.z - lo) * scale))], 1u);
        atomicAdd(&hist[min(4095u, (unsigned)((float)(v.w - lo) * scale))], 1u);
    }
    __syncthreads();
    scan_find(hist, 32,  &s_bin[0], &s_kkv[0], wtot);
    scan_find(hist, 512, &s_bin[1], &s_kkv[1], wtot);
    const unsigned b32 = s_bin[0], b512 = s_bin[1];
    const int kk32 = s_kkv[0], kk512 = s_kkv[1];
    __syncthreads();

    // ---- scan 3: candidates + register-accumulated prefix log sums ----
    float a32 = 0.f, a512 = 0.f;
    #pragma unroll
    for (int p = 0; p < 4; p++) {
        uint4 v = sk4[tid + p * 512];
        unsigned a[4] = {v.x, v.y, v.z, v.w};
        #pragma unroll
        for (int q = 0; q < 4; q++) {
            unsigned kv = a[q];
            unsigned bin = min(4095u, (unsigned)((float)(kv - lo) * scale));
            if (bin < b512) {
                float l = 0.5f * logf(__uint_as_float(kv)) - lnRef;
                a512 += l;
                if (bin < b32) a32 += l;
            }
            if (bin == b32) {
                unsigned idx = atomicAdd(&candn[0], 1u);
                if (idx < CANDCAP) cand[0][idx] = kv;
            }
            if (bin == b512 && b512 != b32) {
                unsigned idx = atomicAdd(&candn[1], 1u);
                if (idx < CANDCAP) cand[1][idx] = kv;
            }
        }
    }
    // block reduce (a32, a512)
    #pragma unroll
    for (int d = 16; d > 0; d >>= 1) {
        a32 += __shfl_xor_sync(0xFFFFFFFFu, a32, d);
        a512 += __shfl_xor_sync(0xFFFFFFFFu, a512, d);
    }
    if (lane == 0) { atomicAdd(&s_pref[0], a32); atomicAdd(&s_pref[1], a512); }
    __syncthreads();

    // exact K via rank count among candidates (duplicate-safe)
    {
        int c0 = (int)min(candn[0], (unsigned)CANDCAP);
        for (int i = tid; i < c0; i += 512) {
            unsigned v = cand[0][i];
            int sm = 0, eq = 0;
            for (int j = 0; j < c0; j++) {
                unsigned w = cand[0][j];
                sm += (w < v); eq += (w == v);
            }
            if (sm < kk32 && kk32 <= sm + eq) sK[0] = v;
        }
        const unsigned* c512arr = (b512 == b32) ? cand[0] : cand[1];
        int c1 = (b512 == b32) ? c0 : (int)min(candn[1], (unsigned)CANDCAP);
        for (int i = tid; i < c1; i += 512) {
            unsigned v = c512arr[i];
            int sm = 0, eq = 0;
            for (int j = 0; j < c1; j++) {
                unsigned w = c512arr[j];
                sm += (w < v); eq += (w == v);
            }
            if (sm < kk512 && kk512 <= sm + eq) sK[1] = v;
        }
    }
    __syncthreads();
    const unsigned K32 = sK[0];
    const unsigned K512 = sK[1];

    // in-bin contributions (tiny candidate arrays)
    {
        int c0 = (int)min(candn[0], (unsigned)CANDCAP);
        for (int i = tid; i < c0; i += 512) {
            unsigned v = cand[0][i];
            if (v < K32) {
                atomicAdd(&s_inlog[0], 0.5f * logf(__uint_as_float(v)) - lnRef);
                atomicAdd(&s_incnt[0], 1);
            }
        }
        const unsigned* c512arr = (b512 == b32) ? cand[0] : cand[1];
        int c1 = (b512 == b32) ? c0 : (int)min(candn[1], (unsigned)CANDCAP);
        for (int i = tid; i < c1; i += 512) {
            unsigned v = c512arr[i];
            if (v < K512) {
                atomicAdd(&s_inlog[1], 0.5f * logf(__uint_as_float(v)) - lnRef);
                atomicAdd(&s_incnt[1], 1);
            }
        }
    }
    __syncthreads();

    if (tid == 0) {
        int cnt32 = (32 - kk32) + s_incnt[0];
        float S32 = s_pref[0] + s_inlog[0]
                  - (float)cnt32 * (0.5f * logf(__uint_as_float(K32)) - lnRef);
        out[OUT_LIDS32 + r] = -32.f / S32;
    } else if (tid == 32) {
        int cnt512 = (512 - kk512) + s_incnt[1];
        float S512 = s_pref[1] + s_inlog[1]
                   - (float)cnt512 * (0.5f * logf(__uint_as_float(K512)) - lnRef);
        out[OUT_LIDS512 + r] = -512.f / S512;
    }
}

// ---------------------------------------------------------------------------
extern "C" void kernel_launch(void* const* d_in, const int* in_sizes, int n_in,
                              void* d_out, int out_size)
{
    const float* z0 = (const float*)d_in[0];
    const float* z1 = (const float*)d_in[1];
    const float* f0 = (const float*)d_in[2];
    const float* f1 = (const float*)d_in[3];
    float* out = (float*)d_out;

    cudaFuncSetAttribute(fused_gemm_kernel,
                         cudaFuncAttributeMaxDynamicSharedMemorySize, GSMEM_DYN);

    // order chosen so ncu's capture slot lands on select_kernel (4th launch)
    prep_kernel<<<N2, 256>>>(z0, z1, f0, f1, out);
    fused_gemm_kernel<<<2 * NTILE, 256, GSMEM_DYN>>>(out);
    loss_final_kernel<<<N2, 128>>>();
    select_kernel<<<N2, 512>>>(out);
    finalize_kernel<<<1, 256>>>(out);
}

// round 16
// speedup vs baseline: 1.1341x; 1.0018x over previous
#include <cuda_runtime.h>
#include <cuda_bf16.h>
#include <cstdint>

#define B4 4096
#define N2 8192
#define DZ 128
#define DF 2048
#define LCOLS 8191
#define NTILE 2080                 // 64*65/2 triangle tiles

// output layout (float32): loss[1], logits[8192*8191], labels[8192], lids_k32[8192], lids_k512[8192]
#define OUT_LOSS    0ull
#define OUT_LOGITS  1ull
#define OUT_LABELS  (1ull + (unsigned long long)N2 * LCOLS)
#define OUT_LIDS32  (OUT_LABELS + N2)
#define OUT_LIDS512 (OUT_LIDS32 + N2)

// scratch (device globals: allocation-free per harness rules)
__device__ __nv_bfloat16 g_fhi[(size_t)N2 * DF];
__device__ __nv_bfloat16 g_flo[(size_t)N2 * DF];
__device__ __nv_bfloat16 g_zhi[N2 * DZ];
__device__ __nv_bfloat16 g_zlo[N2 * DZ];
__device__ float g_fn[N2];
__device__ float g_D[(size_t)N2 * N2];     // 256 MiB
__device__ float g_ls[64 * N2];            // per-(tile-slot,row) exp partial sums
__device__ float g_lossper[N2];
__device__ unsigned g_dmin, g_dmax;        // global off-diag d2 range (uint-ordered)

// ---------------------------------------------------------------------------
// PTX helpers (plain sm_103-safe: mma.sync / ldmatrix / cp.async only)
// ---------------------------------------------------------------------------
__device__ __forceinline__ uint32_t smem_u32(const void* p) {
    uint32_t a;
    asm("{ .reg .u64 t; cvta.to.shared.u64 t, %1; cvt.u32.u64 %0, t; }" : "=r"(a) : "l"(p));
    return a;
}

#define CP_ASYNC16(dst, src) \
    asm volatile("cp.async.cg.shared.global [%0], [%1], 16;" :: "r"(dst), "l"(src) : "memory")
#define CP_COMMIT() asm volatile("cp.async.commit_group;" ::: "memory")
#define CP_WAIT1()  asm volatile("cp.async.wait_group 1;" ::: "memory")
#define CP_WAIT0()  asm volatile("cp.async.wait_group 0;" ::: "memory")

#define LDSM4(r, addr) \
    asm volatile("ldmatrix.sync.aligned.m8n8.x4.shared.b16 {%0,%1,%2,%3}, [%4];" \
        : "=r"((r)[0]), "=r"((r)[1]), "=r"((r)[2]), "=r"((r)[3]) : "r"(addr))

#define MMA16816(d, a, b0, b1) \
    asm volatile("mma.sync.aligned.m16n8k16.row.col.f32.bf16.bf16.f32 " \
        "{%0,%1,%2,%3}, {%4,%5,%6,%7}, {%8,%9}, {%0,%1,%2,%3};" \
        : "+f"((d)[0]), "+f"((d)[1]), "+f"((d)[2]), "+f"((d)[3]) \
        : "r"((a)[0]), "r"((a)[1]), "r"((a)[2]), "r"((a)[3]), "r"(b0), "r"(b1))

// off-diag column mapping (row gi, logical col gj) -> packed col, -1 = diag
__device__ __forceinline__ int colmap(int gi, int gj) {
    if (gi < B4) {
        if (gj >= B4) return gj - B4;
        if (gj == gi) return -1;
        return B4 + gj - (gj > gi ? 1 : 0);
    } else {
        if (gj < B4) return gj;
        if (gj == gi) return -1;
        return gj - (gj > gi ? 1 : 0);
    }
}

// linear tile id -> (br, bc) with 0 <= br <= bc < 64
__device__ __forceinline__ void tri_decode(int t, int& br, int& bc) {
    int row = 0, rem = t;
    #pragma unroll 1
    while (rem >= 64 - row) { rem -= 64 - row; row++; }
    br = row; bc = row + rem;
}

// ---------------------------------------------------------------------------
// prep: f squared norms + bf16 splits (vectorized), z normalize, labels,
// init global d2 range
// ---------------------------------------------------------------------------
__global__ void __launch_bounds__(256) prep_kernel(
    const float* __restrict__ z0, const float* __restrict__ z1,
    const float* __restrict__ f0, const float* __restrict__ f1,
    float* __restrict__ out)
{
    int r = blockIdx.x;
    int tid = threadIdx.x;
    __shared__ float sred[256];

    if (r == 0 && tid == 0) { g_dmin = 0xFFFFFFFFu; g_dmax = 0u; }

    const float* f = (r < B4) ? (f0 + (size_t)r * DF) : (f1 + (size_t)(r - B4) * DF);
    float s = 0.f;
    #pragma unroll
    for (int p = 0; p < 2; p++) {
        int j = tid * 8 + p * 4;               // 256*8 = 2048 exactly
        float4 v = *(const float4*)&f[j];
        s += v.x * v.x + v.y * v.y + v.z * v.z + v.w * v.w;
        __nv_bfloat162 h01 = __floats2bfloat162_rn(v.x, v.y);
        __nv_bfloat162 h23 = __floats2bfloat162_rn(v.z, v.w);
        __nv_bfloat162 l01 = __floats2bfloat162_rn(v.x - __bfloat162float(h01.x),
                                                   v.y - __bfloat162float(h01.y));
        __nv_bfloat162 l23 = __floats2bfloat162_rn(v.z - __bfloat162float(h23.x),
                                                   v.w - __bfloat162float(h23.y));
        *(__nv_bfloat162*)&g_fhi[(size_t)r * DF + j]     = h01;
        *(__nv_bfloat162*)&g_fhi[(size_t)r * DF + j + 2] = h23;
        *(__nv_bfloat162*)&g_flo[(size_t)r * DF + j]     = l01;
        *(__nv_bfloat162*)&g_flo[(size_t)r * DF + j + 2] = l23;
    }
    sred[tid] = s; __syncthreads();
    for (int st = 128; st > 0; st >>= 1) { if (tid < st) sred[tid] += sred[tid + st]; __syncthreads(); }
    if (tid == 0) g_fn[r] = sred[0];
    __syncthreads();

    const float* z = (r < B4) ? (z0 + (size_t)r * DZ) : (z1 + (size_t)(r - B4) * DZ);
    float v = (tid < DZ) ? z[tid] : 0.f;
    sred[tid] = v * v; __syncthreads();
    for (int st = 128; st > 0; st >>= 1) { if (tid < st) sred[tid] += sred[tid + st]; __syncthreads(); }
    float inv = 1.f / fmaxf(sqrtf(sred[0]), 1e-12f);
    if (tid < DZ) {
        float zn = v * inv;
        __nv_bfloat16 h = __float2bfloat16(zn);
        g_zhi[(size_t)r * DZ + tid] = h;
        g_zlo[(size_t)r * DZ + tid] = __float2bfloat16(zn - __bfloat162float(h));
    }
    if (tid == 0) out[OUT_LABELS + r] = (float)(r & (B4 - 1));
}

// ===========================================================================
// shared GEMM building blocks: CTA 128x128, warp 32x64, BK=32, 2-stage,
// 2 CTAs/SM co-residency. ROWB=80 (64B data + 16B pad).
// ===========================================================================
#define GSTG 40960                // Ah 10240 | Al 10240 | Bh 10240 | Bl 10240
#define G_AL 10240
#define G_BH 20480
#define G_BL 30720
#define ROWB 80
#define GSMEM_DYN (2 * GSTG)      // 81920 -> 2 CTAs/SM

template<int KD>
__device__ __forceinline__ void load_stage_g(
    uint32_t sb, const __nv_bfloat16* __restrict__ hi, const __nv_bfloat16* __restrict__ lo,
    int aBase, int bBase, int kt)
{
    int tid = threadIdx.x;
    #pragma unroll
    for (int p = 0; p < 2; p++) {
        int c = tid + p * 256;
        int row = c >> 2, ch = c & 3;
        size_t offA = (size_t)(aBase + row) * KD + kt + ch * 8;
        size_t offB = (size_t)(bBase + row) * KD + kt + ch * 8;
        uint32_t d = sb + row * ROWB + ch * 16;
        CP_ASYNC16(d,        hi + offA);
        CP_ASYNC16(d + G_AL, lo + offA);
        CP_ASYNC16(d + G_BH, hi + offB);
        CP_ASYNC16(d + G_BL, lo + offB);
    }
}

template<int KD>
__device__ __forceinline__ void gemm_mainloop(
    uint32_t sb, const __nv_bfloat16* hi, const __nv_bfloat16* lo,
    int aBase, int bBase, float acc[2][8][4])
{
    const int tid = threadIdx.x, wid = tid >> 5, lane = tid & 31;
    const int warpM = (wid & 3) * 32, warpN = (wid >> 2) * 64;
    const int aRow = lane & 15, aChunk = (lane >> 4) & 1;
    const int bRow = (lane & 7) | ((lane & 16) >> 1);
    const int bChunk = (lane >> 3) & 1;

    load_stage_g<KD>(sb, hi, lo, aBase, bBase, 0);
    CP_COMMIT();

    const int NK = KD / 32;
    for (int it = 0; it < NK; it++) {
        const int s = it & 1;
        if (it + 1 < NK) {
            load_stage_g<KD>(sb + (s ^ 1) * GSTG, hi, lo, aBase, bBase, (it + 1) * 32);
            CP_COMMIT();
            CP_WAIT1();
        } else {
            CP_WAIT0();
        }
        __syncthreads();

        const uint32_t Ab = sb + s * GSTG;
        const uint32_t Bb = Ab + G_BH;
        #pragma unroll
        for (int ks = 0; ks < 2; ks++) {
            uint32_t ah[2][4], al[2][4], bh[4][4], bl[4][4];
            uint32_t aAddr = Ab + (warpM + aRow) * ROWB + ks * 32 + aChunk * 16;
            LDSM4(ah[0], aAddr);
            LDSM4(ah[1], aAddr + 16 * ROWB);
            LDSM4(al[0], aAddr + G_AL);
            LDSM4(al[1], aAddr + G_AL + 16 * ROWB);
            uint32_t bAddr = Bb + (warpN + bRow) * ROWB + ks * 32 + bChunk * 16;
            #pragma unroll
            for (int nt = 0; nt < 4; nt++) {
                LDSM4(bh[nt], bAddr + nt * 16 * ROWB);
                LDSM4(bl[nt], bAddr + (G_BL - G_BH) + nt * 16 * ROWB);
            }
            #pragma unroll
            for (int mt = 0; mt < 2; mt++)
                #pragma unroll
                for (int j = 0; j < 8; j++)
                    MMA16816(acc[mt][j], ah[mt], bh[j >> 1][(j & 1) * 2], bh[j >> 1][(j & 1) * 2 + 1]);
            #pragma unroll
            for (int mt = 0; mt < 2; mt++)
                #pragma unroll
                for (int j = 0; j < 8; j++)
                    MMA16816(acc[mt][j], ah[mt], bl[j >> 1][(j & 1) * 2], bl[j >> 1][(j & 1) * 2 + 1]);
            #pragma unroll
            for (int mt = 0; mt < 2; mt++)
                #pragma unroll
                for (int j = 0; j < 8; j++)
                    MMA16816(acc[mt][j], al[mt], bh[j >> 1][(j & 1) * 2], bh[j >> 1][(j & 1) * 2 + 1]);
        }
        __syncthreads();
    }
}

// ===========================================================================
// fused GEMM kernel: blocks [0, NTILE) = dist tiles, [NTILE, 2*NTILE) = logits
// tiles. Same smem footprint both paths (80 KB dyn), 2 CTAs/SM.
// Dist epilogue also warp-reduces the off-diag d2 range into g_dmin/g_dmax.
// ===========================================================================
__global__ void __launch_bounds__(256, 2) fused_gemm_kernel(float* __restrict__ out)
{
    extern __shared__ char smem[];
    uint32_t sb = smem_u32(smem);
    const int tid = threadIdx.x, wid = tid >> 5, lane = tid & 31;
    const int warpM = (wid & 3) * 32, warpN = (wid >> 2) * 64;
    __shared__ float sNi[128], sNj[128];

    float acc[2][8][4];
    #pragma unroll
    for (int m = 0; m < 2; m++)
        #pragma unroll
        for (int j = 0; j < 8; j++)
            #pragma unroll
            for (int q = 0; q < 4; q++) acc[m][j][q] = 0.f;

    if (blockIdx.x < NTILE) {
        // ------------------------- dist tile -------------------------
        int br, bc;
        tri_decode(blockIdx.x, br, bc);
        const int aBase = br * 128, bBase = bc * 128;

        gemm_mainloop<DF>(sb, &g_fhi[0], &g_flo[0], aBase, bBase, acc);

        if (tid < 128) sNi[tid] = g_fn[aBase + tid];
        else           sNj[tid - 128] = g_fn[bBase + tid - 128];
        __syncthreads();

        float* st = (float*)smem;   // [128][129]
        #pragma unroll
        for (int mt = 0; mt < 2; mt++) {
            const int r0 = warpM + mt * 16 + (lane >> 2);
            #pragma unroll
            for (int j = 0; j < 8; j++) {
                const int c0 = warpN + (j >> 1) * 16 + (j & 1) * 8 + 2 * (lane & 3);
                #pragma unroll
                for (int q = 0; q < 4; q++) {
                    const int rr = r0 + (q >> 1) * 8;
                    const int cc = c0 + (q & 1);
                    st[rr * 129 + cc] = fmaxf(sNi[rr] + sNj[cc] - 2.f * acc[mt][j][q], 0.f);
                }
            }
        }
        __syncthreads();

        // write + warp-local min/max of off-diag d2
        unsigned lmin = 0xFFFFFFFFu, lmax = 0u;
        for (int x = tid; x < 128 * 128; x += 256) {
            int mm = x >> 7, cc = x & 127;
            float v = st[mm * 129 + cc];
            g_D[(size_t)(aBase + mm) * N2 + (bBase + cc)] = v;
            if (!(br == bc && mm == cc)) {
                unsigned kv = __float_as_uint(v);
                lmin = min(lmin, kv);
                lmax = max(lmax, kv);
            }
        }
        #pragma unroll
        for (int d = 16; d > 0; d >>= 1) {
            lmin = min(lmin, __shfl_xor_sync(0xFFFFFFFFu, lmin, d));
            lmax = max(lmax, __shfl_xor_sync(0xFFFFFFFFu, lmax, d));
        }
        if (lane == 0) { atomicMin(&g_dmin, lmin); atomicMax(&g_dmax, lmax); }

        if (bc > br) {
            for (int x = tid; x < 128 * 128; x += 256) {
                int rc = x >> 7, cm = x & 127;
                g_D[(size_t)(bBase + rc) * N2 + (aBase + cm)] = st[cm * 129 + rc];
            }
        }
    } else {
        // ------------------------- logits tile -------------------------
        int br, bc;
        tri_decode(blockIdx.x - NTILE, br, bc);
        const int aBase = br * 128, bBase = bc * 128;

        gemm_mainloop<DZ>(sb, &g_zhi[0], &g_zlo[0], aBase, bBase, acc);

        float* st = (float*)smem;
        #pragma unroll
        for (int mt = 0; mt < 2; mt++) {
            const int r0 = warpM + mt * 16 + (lane >> 2);
            #pragma unroll
            for (int j = 0; j < 8; j++) {
                const int c0 = warpN + (j >> 1) * 16 + (j & 1) * 8 + 2 * (lane & 3);
                #pragma unroll
                for (int q = 0; q < 4; q++)
                    st[(r0 + (q >> 1) * 8) * 129 + c0 + (q & 1)] = 2.f * acc[mt][j][q];
            }
        }
        __syncthreads();

        for (int x = tid; x < 128 * 128; x += 256) {
            int mm = x >> 7, cc = x & 127;
            int col = colmap(aBase + mm, bBase + cc);
            if (col >= 0) out[OUT_LOGITS + (size_t)(aBase + mm) * LCOLS + col] = st[mm * 129 + cc];
        }
        if (bc > br) {
            for (int x = tid; x < 128 * 128; x += 256) {
                int rc = x >> 7, cm = x & 127;
                int col = colmap(bBase + rc, aBase + cm);
                if (col >= 0) out[OUT_LOGITS + (size_t)(bBase + rc) * LCOLS + col] = st[cm * 129 + rc];
            }
        }
        __syncthreads();

        // fused exp + row/col softmax-denominator partials
        for (int x = tid; x < 128 * 128; x += 256) {
            int mm = x >> 7, cc = x & 127;
            float e = __expf(st[mm * 129 + cc]);
            if (br == bc && mm == cc) e = 0.f;     // exclude diagonal
            st[mm * 129 + cc] = e;
        }
        __syncthreads();

        {   // row sums -> slot bc, rows aBase..aBase+127 (2 threads per row)
            int row = tid >> 1, half = tid & 1;
            float s = 0.f;
            #pragma unroll 4
            for (int c2 = half * 64; c2 < half * 64 + 64; c2++) s += st[row * 129 + c2];
            s += __shfl_xor_sync(0xFFFFFFFFu, s, 1);
            if (half == 0) g_ls[(size_t)bc * N2 + aBase + row] = s;
        }
        if (bc > br) {   // col sums -> slot br, rows bBase..bBase+127
            int col = tid >> 1, half = tid & 1;
            float s = 0.f;
            #pragma unroll 4
            for (int r2 = half * 64; r2 < half * 64 + 64; r2++) s += st[r2 * 129 + col];
            s += __shfl_xor_sync(0xFFFFFFFFu, s, 1);
            if (half == 0) g_ls[(size_t)br * N2 + bBase + col] = s;
        }
    }
}

// ---------------------------------------------------------------------------
// loss_final: per row, S = sum of 64 partials; pos = 2*dot(z0n, z1n)
// ---------------------------------------------------------------------------
__global__ void __launch_bounds__(128) loss_final_kernel()
{
    int r = blockIdx.x, tid = threadIdx.x;
    int pr = (r < B4) ? r + B4 : r - B4;

    float a = (float)g_zhi[(size_t)r * DZ + tid] + (float)g_zlo[(size_t)r * DZ + tid];
    float b = (float)g_zhi[(size_t)pr * DZ + tid] + (float)g_zlo[(size_t)pr * DZ + tid];
    float p = a * b;
    float S = (tid < 64) ? g_ls[(size_t)tid * N2 + r] : 0.f;

    #pragma unroll
    for (int d = 16; d > 0; d >>= 1) {
        p += __shfl_xor_sync(0xFFFFFFFFu, p, d);
        S += __shfl_xor_sync(0xFFFFFFFFu, S, d);
    }
    __shared__ float sp[4], sS[4];
    if ((tid & 31) == 0) { sp[tid >> 5] = p; sS[tid >> 5] = S; }
    __syncthreads();
    if (tid == 0) {
        float P = sp[0] + sp[1] + sp[2] + sp[3];
        float SS = sS[0] + sS[1] + sS[2] + sS[3];
        g_lossper[r] = logf(SS) - 2.f * P;
    }
}

__global__ void __launch_bounds__(256) finalize_kernel(float* __restrict__ out)
{
    __shared__ double sred[256];
    int tid = threadIdx.x;
    double s = 0.0;
    for (int j = tid; j < N2; j += 256) s += (double)g_lossper[j];
    sred[tid] = s; __syncthreads();
    for (int st = 128; st > 0; st >>= 1) { if (tid < st) sred[tid] += sred[tid + st]; __syncthreads(); }
    if (tid == 0) out[OUT_LOSS] = (float)(sred[0] / (double)N2);
}

// ---------------------------------------------------------------------------
// select: linear-bin select (GLOBAL bin scale from g_dmin/g_dmax) of rank-32
// and rank-512. 2 key scans: A = load + histogram, B = candidates + register
// prefix log sums. Exact boundary resolve via candidate rank count.
// ---------------------------------------------------------------------------
#define CANDCAP 1024

__device__ __forceinline__ void scan_find(
    const unsigned* __restrict__ hist, int kk,
    unsigned* s_bin, int* s_kk, unsigned* wtot)
{
    int tid = threadIdx.x;
    unsigned c[8], tsum = 0;
    #pragma unroll
    for (int b = 0; b < 8; b++) { c[b] = hist[tid * 8 + b]; tsum += c[b]; }
    unsigned v = tsum;
    #pragma unroll
    for (int d = 1; d < 32; d <<= 1) {
        unsigned n = __shfl_up_sync(0xFFFFFFFFu, v, d);
        if ((tid & 31) >= d) v += n;
    }
    if ((tid & 31) == 31) wtot[tid >> 5] = v;
    __syncthreads();
    if (tid < 16) {
        unsigned t = wtot[tid];
        #pragma unroll
        for (int d = 1; d < 16; d <<= 1) {
            unsigned n = __shfl_up_sync(0xFFFFu, t, d);
            if (tid >= d) t += n;
        }
        wtot[tid] = t;
    }
    __syncthreads();
    unsigned incl = v + ((tid >= 32) ? wtot[(tid >> 5) - 1] : 0u);
    unsigned excl = incl - tsum;
    if ((unsigned)kk > excl && (unsigned)kk <= incl) {
        unsigned cum = excl;
        #pragma unroll
        for (int b = 0; b < 8; b++) {
            if ((unsigned)kk <= cum + c[b]) { *s_bin = tid * 8 + b; *s_kk = kk - (int)cum; break; }
            cum += c[b];
        }
    }
    __syncthreads();
}

__global__ void __launch_bounds__(512) select_kernel(float* __restrict__ out)
{
    int r = blockIdx.x, tid = threadIdx.x;
    int lane = tid & 31;
    __shared__ unsigned skey[N2];           // 32 KB
    __shared__ unsigned hist[4096];         // 16 KB
    __shared__ unsigned cand[2][CANDCAP];   // 8 KB
    __shared__ unsigned candn[2];
    __shared__ unsigned wtot[16];
    __shared__ unsigned s_bin[2];
    __shared__ int s_kkv[2];
    __shared__ unsigned sK[2];
    __shared__ float s_pref[2];
    __shared__ float s_inlog[2];
    __shared__ int   s_incnt[2];

    const unsigned lo = g_dmin;
    const float scale = 4096.0f / ((float)(g_dmax - lo) + 1.0f);
    const float lnRef = 0.5f * logf(fmaxf(__uint_as_float(lo), 1e-30f));

    // ---- scan A: vectorized load + patch diagonal + histogram ----
    #pragma unroll
    for (int b = 0; b < 8; b++) hist[tid + b * 512] = 0u;
    if (tid < 2) { candn[tid] = 0u; s_pref[tid] = 0.f; s_inlog[tid] = 0.f; s_incnt[tid] = 0; }
    __syncthreads();

    const uint4* drow4 = (const uint4*)&g_D[(size_t)r * N2];
    #pragma unroll
    for (int p = 0; p < 4; p++) {
        int j4 = tid + p * 512;                  // uint4 index (2048 total)
        uint4 v = drow4[j4];
        int j = j4 * 4;
        unsigned a[4] = {v.x, v.y, v.z, v.w};
        #pragma unroll
        for (int q = 0; q < 4; q++) {
            unsigned kv = ((j + q) == r) ? 0xFFFFFFFFu : a[q];
            a[q] = kv;
            unsigned bin = min(4095u, (unsigned)((float)(kv - lo) * scale));
            atomicAdd(&hist[bin], 1u);
        }
        *(uint4*)&skey[j] = make_uint4(a[0], a[1], a[2], a[3]);
    }
    __syncthreads();
    scan_find(hist, 32,  &s_bin[0], &s_kkv[0], wtot);
    scan_find(hist, 512, &s_bin[1], &s_kkv[1], wtot);
    const unsigned b32 = s_bin[0], b512 = s_bin[1];
    const int kk32 = s_kkv[0], kk512 = s_kkv[1];
    __syncthreads();

    // ---- scan B: candidates + register-accumulated prefix log sums ----
    const uint4* sk4 = (const uint4*)skey;
    float a32 = 0.f, a512 = 0.f;
    #pragma unroll
    for (int p = 0; p < 4; p++) {
        uint4 v = sk4[tid + p * 512];
        unsigned a[4] = {v.x, v.y, v.z, v.w};
        #pragma unroll
        for (int q = 0; q < 4; q++) {
            unsigned kv = a[q];
            unsigned bin = min(4095u, (unsigned)((float)(kv - lo) * scale));
            if (bin < b512) {
                float l = 0.5f * logf(__uint_as_float(kv)) - lnRef;
                a512 += l;
                if (bin < b32) a32 += l;
            }
            if (bin == b32) {
                unsigned idx = atomicAdd(&candn[0], 1u);
                if (idx < CANDCAP) cand[0][idx] = kv;
            }
            if (bin == b512 && b512 != b32) {
                unsigned idx = atomicAdd(&candn[1], 1u);
                if (idx < CANDCAP) cand[1][idx] = kv;
            }
        }
    }
    #pragma unroll
    for (int d = 16; d > 0; d >>= 1) {
        a32 += __shfl_xor_sync(0xFFFFFFFFu, a32, d);
        a512 += __shfl_xor_sync(0xFFFFFFFFu, a512, d);
    }
    if (lane == 0) { atomicAdd(&s_pref[0], a32); atomicAdd(&s_pref[1], a512); }
    __syncthreads();

    // exact K via rank count among candidates (duplicate-safe)
    {
        int c0 = (int)min(candn[0], (unsigned)CANDCAP);
        for (int i = tid; i < c0; i += 512) {
            unsigned v = cand[0][i];
            int sm = 0, eq = 0;
            for (int j = 0; j < c0; j++) {
                unsigned w = cand[0][j];
                sm += (w < v); eq += (w == v);
            }
            if (sm < kk32 && kk32 <= sm + eq) sK[0] = v;
        }
        const unsigned* c512arr = (b512 == b32) ? cand[0] : cand[1];
        int c1 = (b512 == b32) ? c0 : (int)min(candn[1], (unsigned)CANDCAP);
        for (int i = tid; i < c1; i += 512) {
            unsigned v = c512arr[i];
            int sm = 0, eq = 0;
            for (int j = 0; j < c1; j++) {
                unsigned w = c512arr[j];
                sm += (w < v); eq += (w == v);
            }
            if (sm < kk512 && kk512 <= sm + eq) sK[1] = v;
        }
    }
    __syncthreads();
    const unsigned K32 = sK[0];
    const unsigned K512 = sK[1];

    // in-bin contributions (tiny candidate arrays)
    {
        int c0 = (int)min(candn[0], (unsigned)CANDCAP);
        for (int i = tid; i < c0; i += 512) {
            unsigned v = cand[0][i];
            if (v < K32) {
                atomicAdd(&s_inlog[0], 0.5f * logf(__uint_as_float(v)) - lnRef);
                atomicAdd(&s_incnt[0], 1);
            }
        }
        const unsigned* c512arr = (b512 == b32) ? cand[0] : cand[1];
        int c1 = (b512 == b32) ? c0 : (int)min(candn[1], (unsigned)CANDCAP);
        for (int i = tid; i < c1; i += 512) {
            unsigned v = c512arr[i];
            if (v < K512) {
                atomicAdd(&s_inlog[1], 0.5f * logf(__uint_as_float(v)) - lnRef);
                atomicAdd(&s_incnt[1], 1);
            }
        }
    }
    __syncthreads();

    if (tid == 0) {
        int cnt32 = (32 - kk32) + s_incnt[0];
        float S32 = s_pref[0] + s_inlog[0]
                  - (float)cnt32 * (0.5f * logf(__uint_as_float(K32)) - lnRef);
        out[OUT_LIDS32 + r] = -32.f / S32;
    } else if (tid == 32) {
        int cnt512 = (512 - kk512) + s_incnt[1];
        float S512 = s_pref[1] + s_inlog[1]
                   - (float)cnt512 * (0.5f * logf(__uint_as_float(K512)) - lnRef);
        out[OUT_LIDS512 + r] = -512.f / S512;
    }
}

// ---------------------------------------------------------------------------
extern "C" void kernel_launch(void* const* d_in, const int* in_sizes, int n_in,
                              void* d_out, int out_size)
{
    const float* z0 = (const float*)d_in[0];
    const float* z1 = (const float*)d_in[1];
    const float* f0 = (const float*)d_in[2];
    const float* f1 = (const float*)d_in[3];
    float* out = (float*)d_out;

    cudaFuncSetAttribute(fused_gemm_kernel,
                         cudaFuncAttributeMaxDynamicSharedMemorySize, GSMEM_DYN);

    // order chosen so ncu's capture slot lands on select_kernel (4th launch)
    prep_kernel<<<N2, 256>>>(z0, z1, f0, f1, out);
    fused_gemm_kernel<<<2 * NTILE, 256, GSMEM_DYN>>>(out);
    loss_final_kernel<<<N2, 128>>>();
    select_kernel<<<N2, 512>>>(out);
    finalize_kernel<<<1, 256>>>(out);
}